// round 14
// baseline (speedup 1.0000x reference)
#include <cuda_runtime.h>
#include <cuda.h>
#include <cuda_bf16.h>
#include <cstdint>

// ============================================================================
// Problem constants
// ============================================================================
#define K_DIM   1024
#define M_OUT   1024
#define N_MAX   32768

#define TM      128       // CTA tile rows
#define TN      128       // CTA tile cols
#define KC      128       // K elems per mainloop chunk (two 64-col SW128 sub-tiles)
#define STAGES  3
#define KITERS  (K_DIM / KC)    // 8 chunks per tile
#define NTHREADS 384            // 12 warps: 8 compute + 1 TMA producer + 3 quant
#define NTILE_X (M_OUT / TN)    // 8 n-tiles

// SMEM layout (dynamic)
#define SM_MBAR  16                    // ring: full at 16+16s, empty at 24+16s
#define SM_A     1024
#define SUB_BYTES   16384              // one 128-row x 64-col bf16 sub-tile
#define STAGE_BYTES 65536              // A(2 sub) + B(2 sub)
#define SMEM_TOTAL (1024 + STAGES * STAGE_BYTES)   // 197632 -> 1 CTA/SM

// Prepass (absmax x+w, then w-quant only): 6 blocks/SM co-resident
#define XB 864
#define WB 24
#define PB (XB + WB)

// ============================================================================
// Scratch (__device__ globals; no allocation allowed)
// ============================================================================
__device__ __align__(1024) __nv_bfloat16 g_qx[(size_t)N_MAX * K_DIM];   // 64 MB
__device__ __align__(1024) __nv_bfloat16 g_qw[(size_t)M_OUT * K_DIM];   //  2 MB
__device__ unsigned g_absmax[2] = {0u, 0u};
__device__ unsigned g_arrive = 0u;
__device__ unsigned g_done   = 0u;
__device__ unsigned g_gdone  = 0u;
__device__ unsigned g_qflag[512];      // per-A-m-block ready flags (0 / 2)

// ============================================================================
// PTX helpers (base-target safe on sm_103)
// ============================================================================
__device__ __forceinline__ uint32_t smem_u32(const void* p) {
    return (uint32_t)__cvta_generic_to_shared(p);
}
__device__ __forceinline__ uint32_t elect1() {
    uint32_t pred;
    asm volatile("{\n\t.reg .pred p;\n\telect.sync _|p, 0xFFFFFFFF;\n\t"
                 "selp.b32 %0, 1, 0, p;\n\t}" : "=r"(pred));
    return pred;
}
__device__ __forceinline__ void mbar_init(uint32_t mbar, uint32_t count) {
    asm volatile("mbarrier.init.shared.b64 [%0], %1;" :: "r"(mbar), "r"(count) : "memory");
}
__device__ __forceinline__ void mbar_expect_tx(uint32_t mbar, uint32_t bytes) {
    asm volatile("mbarrier.arrive.expect_tx.shared.b64 _, [%0], %1;"
                 :: "r"(mbar), "r"(bytes) : "memory");
}
__device__ __forceinline__ void mbar_arrive(uint32_t mbar) {
    asm volatile("mbarrier.arrive.shared.b64 _, [%0];" :: "r"(mbar) : "memory");
}
__device__ __forceinline__ void mbar_wait(uint32_t mbar, uint32_t parity) {
    uint32_t done;
    asm volatile("{\n\t.reg .pred p;\n\t"
                 "mbarrier.try_wait.parity.acquire.cta.shared::cta.b64 p, [%1], %2;\n\t"
                 "selp.b32 %0, 1, 0, p;\n\t}"
                 : "=r"(done) : "r"(mbar), "r"(parity) : "memory");
    while (!done) {
        asm volatile("{\n\t.reg .pred p;\n\t"
                     "mbarrier.try_wait.parity.acquire.cta.shared::cta.b64 p, [%1], %2, 0x989680;\n\t"
                     "selp.b32 %0, 1, 0, p;\n\t}"
                     : "=r"(done) : "r"(mbar), "r"(parity) : "memory");
    }
}
__device__ __forceinline__ void tma2d(uint32_t dst, const CUtensorMap* tm,
                                      int cx, int cy, uint32_t mbar) {
    asm volatile("cp.async.bulk.tensor.2d.shared::cta.global.tile.mbarrier::complete_tx::bytes "
                 "[%0], [%1, {%2, %3}], [%4];"
                 :: "r"(dst), "l"(tm), "r"(cx), "r"(cy), "r"(mbar) : "memory");
}
__device__ __forceinline__ void ldsm4(uint32_t* r, uint32_t addr) {
    asm volatile("ldmatrix.sync.aligned.m8n8.x4.shared.b16 {%0,%1,%2,%3}, [%4];"
                 : "=r"(r[0]), "=r"(r[1]), "=r"(r[2]), "=r"(r[3]) : "r"(addr));
}
// legacy HMMA m16n8k16 bf16 -> f32 (int8 codes exact in bf16, accum < 2^24 exact
// in f32 -> bit-identical to int32 reference GEMM)
__device__ __forceinline__ void mma16816(float* c, const uint32_t* a, const uint32_t* b) {
    asm volatile("mma.sync.aligned.m16n8k16.row.col.f32.bf16.bf16.f32 "
                 "{%0,%1,%2,%3}, {%4,%5,%6,%7}, {%8,%9}, {%0,%1,%2,%3};"
                 : "+f"(c[0]), "+f"(c[1]), "+f"(c[2]), "+f"(c[3])
                 : "r"(a[0]), "r"(a[1]), "r"(a[2]), "r"(a[3]), "r"(b[0]), "r"(b[1]));
}
__device__ __forceinline__ uint2 quant4(float4 v, float inv) {
    float q0 = fminf(fmaxf(rintf(v.x * inv), -127.0f), 127.0f);
    float q1 = fminf(fmaxf(rintf(v.y * inv), -127.0f), 127.0f);
    float q2 = fminf(fmaxf(rintf(v.z * inv), -127.0f), 127.0f);
    float q3 = fminf(fmaxf(rintf(v.w * inv), -127.0f), 127.0f);
    __nv_bfloat162 p01 = __floats2bfloat162_rn(q0, q1);
    __nv_bfloat162 p23 = __floats2bfloat162_rn(q2, q3);
    uint2 o;
    o.x = *reinterpret_cast<uint32_t*>(&p01);
    o.y = *reinterpret_cast<uint32_t*>(&p23);
    return o;
}

// ============================================================================
// Prepass: absmax over x and w -> grid barrier -> quantize w ONLY (x quant
// happens on-the-fly inside the GEMM kernel, overlapped with compute).
// ============================================================================
__global__ void __launch_bounds__(256, 6) prepass_kernel(
    const float4* __restrict__ x, int n4x,
    const float4* __restrict__ w, uint2* __restrict__ qw, int n4w,
    unsigned* __restrict__ am)
{
    const float4* in;
    int n4, nb, bid;
    unsigned* dst;
    bool is_w = (int)blockIdx.x >= XB;
    if (!is_w) { in = x; n4 = n4x; nb = XB; bid = blockIdx.x; dst = am; }
    else { in = w; n4 = n4w; nb = WB; bid = blockIdx.x - XB; dst = am + 1; }

    const int stride = nb * blockDim.x;
    const int i0 = bid * blockDim.x + threadIdx.x;

    // ---- phase 1: absmax (MLP 8) ----
    float m = 0.0f;
    int i = i0;
    for (; i + 7 * stride < n4; i += 8 * stride) {
        float pm[8];
#pragma unroll
        for (int u = 0; u < 8; u++) {
            float4 v = in[i + u * stride];
            pm[u] = fmaxf(fmaxf(fabsf(v.x), fabsf(v.y)), fmaxf(fabsf(v.z), fabsf(v.w)));
        }
        float m01 = fmaxf(pm[0], pm[1]), m23 = fmaxf(pm[2], pm[3]);
        float m45 = fmaxf(pm[4], pm[5]), m67 = fmaxf(pm[6], pm[7]);
        m = fmaxf(m, fmaxf(fmaxf(m01, m23), fmaxf(m45, m67)));
    }
    for (; i < n4; i += stride) {
        float4 v = in[i];
        m = fmaxf(m, fmaxf(fmaxf(fabsf(v.x), fabsf(v.y)), fmaxf(fabsf(v.z), fabsf(v.w))));
    }
#pragma unroll
    for (int o = 16; o > 0; o >>= 1)
        m = fmaxf(m, __shfl_xor_sync(0xFFFFFFFFu, m, o));
    if ((threadIdx.x & 31) == 0) atomicMax(dst, __float_as_uint(m));

    // ---- grid barrier (all PB blocks co-resident: 6 blocks/SM) ----
    __syncthreads();
    if (threadIdx.x == 0) {
        __threadfence();
        atomicAdd(&g_arrive, 1u);
        while (*(volatile unsigned*)&g_arrive < PB) { }
        __threadfence();
    }
    __syncthreads();

    // ---- phase 2: quantize w only (x is quantized inside the GEMM) ----
    if (is_w) {
        float inv = 127.0f / __uint_as_float(*(volatile unsigned*)dst);
        for (i = i0; i < n4; i += stride)
            qw[i] = quant4(in[i], inv);
    }

    // ---- reset counters for deterministic graph replay ----
    __syncthreads();
    if (threadIdx.x == 0) {
        unsigned t = atomicAdd(&g_done, 1u);
        if (t == PB - 1) {
            g_arrive = 0u;
            g_done = 0u;
            __threadfence();
        }
    }
}

// ============================================================================
// PERSISTENT GEMM with on-the-fly A quantization.
//   12 warps: 0-7 compute (32m x 64n, R12-proven mainloop), 8 TMA producer,
//   9-11 quantizers (statically assigned A m-blocks -> g_qx + flag).
//   Producer gates each tile's loads on its m-block flag.
// ============================================================================
__global__ void __launch_bounds__(NTHREADS, 1) gemm_kernel(
    const __grid_constant__ CUtensorMap tmA,
    const __grid_constant__ CUtensorMap tmB,
    const float4* __restrict__ x,
    const float* __restrict__ bias,
    float* __restrict__ out,
    const unsigned* __restrict__ absmax_bits,
    int ntiles, int nblocks)
{
    extern __shared__ __align__(1024) char smem[];
    uint32_t sb = smem_u32(smem);
    const int tid = threadIdx.x;
    const int wid = tid >> 5;
    const int lid = tid & 31;
    const int ncta = gridDim.x;

    if (tid == 0) {
        for (int s = 0; s < STAGES; s++) {
            mbar_init(sb + SM_MBAR + 16 * s, 1);       // full (producer expect_tx)
            mbar_init(sb + SM_MBAR + 16 * s + 8, 8);   // empty (8 compute warps)
        }
        asm volatile("fence.proxy.async.shared::cta;" ::: "memory");
    }
    __syncthreads();

    if (wid >= 9) {                       // -------- 3 quantizer warps --------
        const int tq = tid - 288;         // 0..95
        const float inv = 127.0f / __uint_as_float(absmax_bits[0]);
        const int blo = ((int)blockIdx.x * nblocks) / ncta;
        const int bhi = (((int)blockIdx.x + 1) * nblocks) / ncta;
        const int blk4 = TM * K_DIM / 4;  // 32768 float4 per block
        for (int blk = blo; blk < bhi; blk++) {
            const float4* src = x + (size_t)blk * blk4;
            uint2* dst = (uint2*)g_qx + (size_t)blk * blk4;
            int i = tq;
            for (; i + 15 * 96 < blk4; i += 16 * 96) {   // MLP 16
                float4 v[16];
#pragma unroll
                for (int u = 0; u < 16; u++) v[u] = src[i + u * 96];
#pragma unroll
                for (int u = 0; u < 16; u++) dst[i + u * 96] = quant4(v[u], inv);
            }
            for (; i < blk4; i += 96)
                dst[i] = quant4(src[i], inv);
            // publish: all 96 threads' stores must complete before flag
            __threadfence();
            asm volatile("bar.sync 1, 96;" ::: "memory");  // quant warps only
            if (tq == 0) atomicExch(&g_qflag[blk], 2u);
        }
    } else if (wid == 8) {                // -------- TMA producer --------
        if (elect1()) {
            int s = 0, ph = 1;
            for (int t = blockIdx.x; t < ntiles; t += ncta) {
                const int m_base = (t >> 3) * TM;          // NTILE_X == 8
                const int n_base = (t & 7) * TN;
                // gate on A m-block readiness
                const int blk = t >> 3;
                unsigned f;
                do {
                    asm volatile("ld.global.cg.u32 %0, [%1];" : "=r"(f) : "l"(&g_qflag[blk]));
                    if (f != 2u) __nanosleep(64);
                } while (f != 2u);
                asm volatile("fence.proxy.async;" ::: "memory");

                for (int kc = 0; kc < KITERS; kc++) {
                    mbar_wait(sb + SM_MBAR + 16 * s + 8, ph);
                    mbar_expect_tx(sb + SM_MBAR + 16 * s, STAGE_BYTES);
                    uint32_t base = sb + SM_A + s * STAGE_BYTES;
                    uint32_t mb = sb + SM_MBAR + 16 * s;
                    tma2d(base,                 &tmA, kc * KC,      m_base, mb);
                    tma2d(base + SUB_BYTES,     &tmA, kc * KC + 64, m_base, mb);
                    tma2d(base + 2 * SUB_BYTES, &tmB, kc * KC,      n_base, mb);
                    tma2d(base + 3 * SUB_BYTES, &tmB, kc * KC + 64, n_base, mb);
                    if (++s == STAGES) { s = 0; ph ^= 1; }
                }
            }
        }
    } else {                              // -------- 8 compute warps (R12 exact) ----
        const int m0 = (wid >> 1) * 32;
        const int n0 = (wid & 1) * 64;

        const int a_row = lid & 15;
        const int a_cof = (lid >> 4) << 4;
        const int b_row = ((lid >> 4) << 3) + (lid & 7);
        const int b_cof = ((lid >> 3) & 1) << 4;

        float acc[2][8][4];
        uint32_t af[2][2][4];
        uint32_t bf[2][4][4];

        auto loadfrag = [&](int buf, uint32_t stage, int step) {
            int st = step >> 2;
            int kk = step & 3;
            uint32_t baseA = stage + st * SUB_BYTES;
            uint32_t baseB = stage + (2 + st) * SUB_BYTES;
#pragma unroll
            for (int mt = 0; mt < 2; mt++) {
                int r = m0 + mt * 16 + a_row;
                int c = kk * 32 + a_cof;
                ldsm4(af[buf][mt], baseA + r * 128 + (c ^ ((r & 7) << 4)));
            }
#pragma unroll
            for (int np = 0; np < 4; np++) {
                int r = n0 + np * 16 + b_row;
                int c = kk * 32 + b_cof;
                ldsm4(bf[buf][np], baseB + r * 128 + (c ^ ((r & 7) << 4)));
            }
        };
        auto mmastep = [&](int buf) {
#pragma unroll
            for (int mt = 0; mt < 2; mt++)
#pragma unroll
                for (int nt = 0; nt < 8; nt++)
                    mma16816(acc[mt][nt], af[buf][mt], &bf[buf][nt >> 1][(nt & 1) * 2]);
        };

        const float scale = (__uint_as_float(absmax_bits[0]) / 127.0f) *
                            (__uint_as_float(absmax_bits[1]) / 127.0f);
        const int r4 = lid >> 2;
        const int c2 = (lid & 3) * 2;

        int s = 0, ph = 0;
        for (int t = blockIdx.x; t < ntiles; t += ncta) {
            const int m_base = (t >> 3) * TM;
            const int n_base = (t & 7) * TN;

#pragma unroll
            for (int mt = 0; mt < 2; mt++)
#pragma unroll
                for (int nt = 0; nt < 8; nt++)
#pragma unroll
                    for (int j = 0; j < 4; j++) acc[mt][nt][j] = 0.0f;

            mbar_wait(sb + SM_MBAR + 16 * s, ph);
            uint32_t stage = sb + SM_A + s * STAGE_BYTES;
            loadfrag(0, stage, 0);

            for (int kc = 0; kc < KITERS; kc++) {
#pragma unroll
                for (int step = 0; step < 8; step++) {
                    const int pb = step & 1;
                    if (step < 7) {
                        loadfrag(pb ^ 1, stage, step + 1);
                    } else {
                        if (lid == 0) mbar_arrive(sb + SM_MBAR + 16 * s + 8);
                        if (++s == STAGES) { s = 0; ph ^= 1; }
                        if (kc < KITERS - 1) {
                            mbar_wait(sb + SM_MBAR + 16 * s, ph);
                            stage = sb + SM_A + s * STAGE_BYTES;
                            loadfrag(pb ^ 1, stage, 0);
                        }
                    }
                    mmastep(pb);
                }
            }

            // epilogue (producer already filling next tile's stages)
#pragma unroll
            for (int mt = 0; mt < 2; mt++) {
#pragma unroll
                for (int nt = 0; nt < 8; nt++) {
                    int cn = n0 + nt * 8 + c2;
                    float b0 = bias[n_base + cn];
                    float b1 = bias[n_base + cn + 1];
                    int gm = m_base + m0 + mt * 16 + r4;
                    float2 v0, v1;
                    v0.x = acc[mt][nt][0] * scale + b0;
                    v0.y = acc[mt][nt][1] * scale + b1;
                    v1.x = acc[mt][nt][2] * scale + b0;
                    v1.y = acc[mt][nt][3] * scale + b1;
                    *reinterpret_cast<float2*>(out + (size_t)gm * M_OUT + n_base + cn) = v0;
                    *reinterpret_cast<float2*>(out + (size_t)(gm + 8) * M_OUT + n_base + cn) = v1;
                }
            }
        }
    }

    // ---- reset flags for deterministic graph replay (last CTA out) ----
    __syncthreads();
    if (tid == 0) {
        __threadfence();
        unsigned t = atomicAdd(&g_gdone, 1u);
        if (t == (unsigned)ncta - 1) {
            for (int b = 0; b < nblocks; b++) g_qflag[b] = 0u;
            g_gdone = 0u;
            __threadfence();
        }
    }
}

// ============================================================================
// Host launch
// ============================================================================
typedef CUresult (*tmap_encode_fn)(
    CUtensorMap*, CUtensorMapDataType, cuuint32_t, void*,
    const cuuint64_t*, const cuuint64_t*, const cuuint32_t*, const cuuint32_t*,
    CUtensorMapInterleave, CUtensorMapSwizzle, CUtensorMapL2promotion, CUtensorMapFloatOOBfill);

extern "C" void kernel_launch(void* const* d_in, const int* in_sizes, int n_in,
                              void* d_out, int out_size) {
    const float* x    = (const float*)d_in[0];
    const float* w    = (const float*)d_in[1];
    const float* bias = (const float*)d_in[2];
    float* out = (float*)d_out;

    int n_rows = in_sizes[0] / K_DIM;       // 32768
    int n4x = in_sizes[0] / 4;
    int n4w = in_sizes[1] / 4;
    int ntiles = (n_rows / TM) * NTILE_X;   // 2048
    int nblocks = n_rows / TM;              // 256

    void *qx_ptr, *qw_ptr, *am_ptr;
    cudaGetSymbolAddress(&qx_ptr, g_qx);
    cudaGetSymbolAddress(&qw_ptr, g_qw);
    cudaGetSymbolAddress(&am_ptr, g_absmax);
    unsigned* am = (unsigned*)am_ptr;

    prepass_kernel<<<PB, 256>>>((const float4*)x, n4x,
                                (const float4*)w, (uint2*)qw_ptr, n4w, am);

    void* fp = nullptr;
    cudaDriverEntryPointQueryResult qr;
#if CUDART_VERSION >= 12050
    cudaGetDriverEntryPointByVersion("cuTensorMapEncodeTiled", &fp, 12000,
                                     cudaEnableDefault, &qr);
#else
    cudaGetDriverEntryPoint("cuTensorMapEncodeTiled", &fp, cudaEnableDefault, &qr);
#endif
    tmap_encode_fn encode = (tmap_encode_fn)fp;

    CUtensorMap tmA, tmB;
    {
        cuuint64_t dims[2]   = {K_DIM, (cuuint64_t)n_rows};
        cuuint64_t stride[1] = {K_DIM * sizeof(__nv_bfloat16)};
        cuuint32_t box[2]    = {64, TM};
        cuuint32_t es[2]     = {1, 1};
        encode(&tmA, CU_TENSOR_MAP_DATA_TYPE_BFLOAT16, 2, qx_ptr, dims, stride, box, es,
               CU_TENSOR_MAP_INTERLEAVE_NONE, CU_TENSOR_MAP_SWIZZLE_128B,
               CU_TENSOR_MAP_L2_PROMOTION_L2_128B, CU_TENSOR_MAP_FLOAT_OOB_FILL_NONE);
    }
    {
        cuuint64_t dims[2]   = {K_DIM, M_OUT};
        cuuint64_t stride[1] = {K_DIM * sizeof(__nv_bfloat16)};
        cuuint32_t box[2]    = {64, TN};
        cuuint32_t es[2]     = {1, 1};
        encode(&tmB, CU_TENSOR_MAP_DATA_TYPE_BFLOAT16, 2, qw_ptr, dims, stride, box, es,
               CU_TENSOR_MAP_INTERLEAVE_NONE, CU_TENSOR_MAP_SWIZZLE_128B,
               CU_TENSOR_MAP_L2_PROMOTION_L2_128B, CU_TENSOR_MAP_FLOAT_OOB_FILL_NONE);
    }

    int nsm = 148;
    cudaDeviceGetAttribute(&nsm, cudaDevAttrMultiProcessorCount, 0);

    cudaFuncSetAttribute(gemm_kernel, cudaFuncAttributeMaxDynamicSharedMemorySize, SMEM_TOTAL);
    gemm_kernel<<<nsm, NTHREADS, SMEM_TOTAL>>>(tmA, tmB, (const float4*)x,
                                               bias, out, am, ntiles, nblocks);
}

// round 15
// speedup vs baseline: 1.2462x; 1.2462x over previous
#include <cuda_runtime.h>
#include <cuda.h>
#include <cuda_bf16.h>
#include <cstdint>

// ============================================================================
// Problem constants
// ============================================================================
#define K_DIM   1024
#define M_OUT   1024
#define N_MAX   32768

#define TM      128       // CTA tile rows
#define TN      128       // CTA tile cols
#define KC      128       // K elems per mainloop chunk (two 64-col SW128 sub-tiles)
#define STAGES  3
#define KITERS  (K_DIM / KC)    // 8 chunks per tile
#define NTHREADS 288            // 9 warps: 8 compute (32m x 64n each) + 1 TMA
#define NTILE_X (M_OUT / TN)    // 8 n-tiles

// SMEM layout (dynamic)
#define SM_MBAR  16                    // ring: full at 16+16s, empty at 24+16s
#define SM_A     1024
#define SUB_BYTES   16384              // one 128-row x 64-col bf16 sub-tile
#define STAGE_BYTES 65536              // A(2 sub) + B(2 sub)
#define SMEM_TOTAL (1024 + STAGES * STAGE_BYTES)   // 197632 < 227KB

// Persistent prepass grid: 6 blocks/SM x 148 SMs = 888, co-resident
#define XB 864
#define WB 24
#define PB (XB + WB)

// ============================================================================
// Scratch (__device__ globals; no allocation allowed)
// ============================================================================
__device__ __align__(1024) __nv_bfloat16 g_qx[(size_t)N_MAX * K_DIM];   // 64 MB
__device__ __align__(1024) __nv_bfloat16 g_qw[(size_t)M_OUT * K_DIM];   //  2 MB
__device__ unsigned g_absmax[2] = {0u, 0u};
__device__ unsigned g_arrive = 0u;
__device__ unsigned g_done   = 0u;

// ============================================================================
// PTX helpers (base-target safe on sm_103)
// ============================================================================
__device__ __forceinline__ uint32_t smem_u32(const void* p) {
    return (uint32_t)__cvta_generic_to_shared(p);
}
__device__ __forceinline__ uint32_t elect1() {
    uint32_t pred;
    asm volatile("{\n\t.reg .pred p;\n\telect.sync _|p, 0xFFFFFFFF;\n\t"
                 "selp.b32 %0, 1, 0, p;\n\t}" : "=r"(pred));
    return pred;
}
__device__ __forceinline__ void mbar_init(uint32_t mbar, uint32_t count) {
    asm volatile("mbarrier.init.shared.b64 [%0], %1;" :: "r"(mbar), "r"(count) : "memory");
}
__device__ __forceinline__ void mbar_expect_tx(uint32_t mbar, uint32_t bytes) {
    asm volatile("mbarrier.arrive.expect_tx.shared.b64 _, [%0], %1;"
                 :: "r"(mbar), "r"(bytes) : "memory");
}
__device__ __forceinline__ void mbar_arrive(uint32_t mbar) {
    asm volatile("mbarrier.arrive.shared.b64 _, [%0];" :: "r"(mbar) : "memory");
}
__device__ __forceinline__ void mbar_wait(uint32_t mbar, uint32_t parity) {
    uint32_t done;
    asm volatile("{\n\t.reg .pred p;\n\t"
                 "mbarrier.try_wait.parity.acquire.cta.shared::cta.b64 p, [%1], %2;\n\t"
                 "selp.b32 %0, 1, 0, p;\n\t}"
                 : "=r"(done) : "r"(mbar), "r"(parity) : "memory");
    while (!done) {
        asm volatile("{\n\t.reg .pred p;\n\t"
                     "mbarrier.try_wait.parity.acquire.cta.shared::cta.b64 p, [%1], %2, 0x989680;\n\t"
                     "selp.b32 %0, 1, 0, p;\n\t}"
                     : "=r"(done) : "r"(mbar), "r"(parity) : "memory");
    }
}
__device__ __forceinline__ void tma2d(uint32_t dst, const CUtensorMap* tm,
                                      int cx, int cy, uint32_t mbar) {
    asm volatile("cp.async.bulk.tensor.2d.shared::cta.global.tile.mbarrier::complete_tx::bytes "
                 "[%0], [%1, {%2, %3}], [%4];"
                 :: "r"(dst), "l"(tm), "r"(cx), "r"(cy), "r"(mbar) : "memory");
}
__device__ __forceinline__ void ldsm4(uint32_t* r, uint32_t addr) {
    asm volatile("ldmatrix.sync.aligned.m8n8.x4.shared.b16 {%0,%1,%2,%3}, [%4];"
                 : "=r"(r[0]), "=r"(r[1]), "=r"(r[2]), "=r"(r[3]) : "r"(addr));
}
// legacy HMMA m16n8k16 bf16 -> f32 (int8 codes exact in bf16, accum < 2^24 exact
// in f32 -> bit-identical to int32 reference GEMM)
__device__ __forceinline__ void mma16816(float* c, const uint32_t* a, const uint32_t* b) {
    asm volatile("mma.sync.aligned.m16n8k16.row.col.f32.bf16.bf16.f32 "
                 "{%0,%1,%2,%3}, {%4,%5,%6,%7}, {%8,%9}, {%0,%1,%2,%3};"
                 : "+f"(c[0]), "+f"(c[1]), "+f"(c[2]), "+f"(c[3])
                 : "r"(a[0]), "r"(a[1]), "r"(a[2]), "r"(a[3]), "r"(b[0]), "r"(b[1]));
}
__device__ __forceinline__ uint2 quant4(float4 v, float inv) {
    float q0 = fminf(fmaxf(rintf(v.x * inv), -127.0f), 127.0f);
    float q1 = fminf(fmaxf(rintf(v.y * inv), -127.0f), 127.0f);
    float q2 = fminf(fmaxf(rintf(v.z * inv), -127.0f), 127.0f);
    float q3 = fminf(fmaxf(rintf(v.w * inv), -127.0f), 127.0f);
    __nv_bfloat162 p01 = __floats2bfloat162_rn(q0, q1);
    __nv_bfloat162 p23 = __floats2bfloat162_rn(q2, q3);
    uint2 o;
    o.x = *reinterpret_cast<uint32_t*>(&p01);
    o.y = *reinterpret_cast<uint32_t*>(&p23);
    return o;
}

// ============================================================================
// Persistent fused prepass (6 CTAs/SM): absmax -> grid barrier -> quantize.
// Phase 2 iterates TOP-DOWN: phase 1's most recently read (= highest-index)
// data is still L2-resident at the barrier, so the reversed re-read hits L2
// instead of DRAM for a large fraction of the 128MB x tensor.
// ============================================================================
__global__ void __launch_bounds__(256, 6) prepass_kernel(
    const float4* __restrict__ x, uint2* __restrict__ qx, int n4x,
    const float4* __restrict__ w, uint2* __restrict__ qw, int n4w,
    unsigned* __restrict__ am)
{
    const float4* in; uint2* outq;
    int n4, nb, bid;
    unsigned* dst;
    if ((int)blockIdx.x < XB) { in = x; outq = qx; n4 = n4x; nb = XB; bid = blockIdx.x; dst = am; }
    else { in = w; outq = qw; n4 = n4w; nb = WB; bid = blockIdx.x - XB; dst = am + 1; }

    const int stride = nb * blockDim.x;
    const int i0 = bid * blockDim.x + threadIdx.x;

    // ---- phase 1: absmax (MLP 8), ascending ----
    float m = 0.0f;
    int i = i0;
    for (; i + 7 * stride < n4; i += 8 * stride) {
        float pm[8];
#pragma unroll
        for (int u = 0; u < 8; u++) {
            float4 v = in[i + u * stride];
            pm[u] = fmaxf(fmaxf(fabsf(v.x), fabsf(v.y)), fmaxf(fabsf(v.z), fabsf(v.w)));
        }
        float m01 = fmaxf(pm[0], pm[1]), m23 = fmaxf(pm[2], pm[3]);
        float m45 = fmaxf(pm[4], pm[5]), m67 = fmaxf(pm[6], pm[7]);
        m = fmaxf(m, fmaxf(fmaxf(m01, m23), fmaxf(m45, m67)));
    }
    for (; i < n4; i += stride) {
        float4 v = in[i];
        m = fmaxf(m, fmaxf(fmaxf(fabsf(v.x), fabsf(v.y)), fmaxf(fabsf(v.z), fabsf(v.w))));
    }
#pragma unroll
    for (int o = 16; o > 0; o >>= 1)
        m = fmaxf(m, __shfl_xor_sync(0xFFFFFFFFu, m, o));
    if ((threadIdx.x & 31) == 0) atomicMax(dst, __float_as_uint(m));

    // ---- grid barrier (all PB blocks co-resident: 6 blocks/SM) ----
    __syncthreads();
    if (threadIdx.x == 0) {
        __threadfence();
        atomicAdd(&g_arrive, 1u);
        while (*(volatile unsigned*)&g_arrive < PB) { }
        __threadfence();
    }
    __syncthreads();

    // ---- phase 2: quantize (MLP 8), DESCENDING for L2 reuse ----
    {
        float inv = 127.0f / __uint_as_float(*(volatile unsigned*)dst);
        int nit = (i0 < n4) ? ((n4 - i0 - 1) / stride + 1) : 0;
        int k = nit;
        // peel remainder from the top end first (most recently cached)
        while (k & 7) {
            --k;
            int idx = i0 + k * stride;
            outq[idx] = quant4(in[idx], inv);
        }
        while (k > 0) {
            k -= 8;
            float4 v[8];
#pragma unroll
            for (int u = 0; u < 8; u++) v[u] = in[i0 + (k + u) * stride];
#pragma unroll
            for (int u = 0; u < 8; u++) outq[i0 + (k + u) * stride] = quant4(v[u], inv);
        }
    }

    // ---- reset counters for deterministic graph replay ----
    __syncthreads();
    if (threadIdx.x == 0) {
        unsigned t = atomicAdd(&g_done, 1u);
        if (t == PB - 1) {
            g_arrive = 0u;
            g_done = 0u;
            __threadfence();
        }
    }
}

// ============================================================================
// PERSISTENT GEMM  out[m][n] = acc(m,n)*(sx*sw) + bias[n]   (R12-proven)
//   grid = #SMs; producer streams TMA continuously across tile boundaries.
//   8 compute warps 4(m)x2(n), 32x64 each.  SW128 swizzle: c ^ ((r&7)<<4).
// ============================================================================
__global__ void __launch_bounds__(NTHREADS, 1) gemm_kernel(
    const __grid_constant__ CUtensorMap tmA,
    const __grid_constant__ CUtensorMap tmB,
    const float* __restrict__ bias,
    float* __restrict__ out,
    const unsigned* __restrict__ absmax_bits,
    int ntiles)
{
    extern __shared__ __align__(1024) char smem[];
    uint32_t sb = smem_u32(smem);
    const int tid = threadIdx.x;
    const int wid = tid >> 5;
    const int lid = tid & 31;

    if (tid == 0) {
        for (int s = 0; s < STAGES; s++) {
            mbar_init(sb + SM_MBAR + 16 * s, 1);       // full (producer expect_tx)
            mbar_init(sb + SM_MBAR + 16 * s + 8, 8);   // empty (8 compute warps)
        }
        asm volatile("fence.proxy.async.shared::cta;" ::: "memory");
    }
    __syncthreads();

    if (wid == 8) {                       // -------- persistent TMA producer --------
        if (elect1()) {
            int s = 0, ph = 1;
            for (int t = blockIdx.x; t < ntiles; t += gridDim.x) {
                const int m_base = (t >> 3) * TM;          // NTILE_X == 8
                const int n_base = (t & 7) * TN;
                for (int kc = 0; kc < KITERS; kc++) {
                    mbar_wait(sb + SM_MBAR + 16 * s + 8, ph);
                    mbar_expect_tx(sb + SM_MBAR + 16 * s, STAGE_BYTES);
                    uint32_t base = sb + SM_A + s * STAGE_BYTES;
                    uint32_t mb = sb + SM_MBAR + 16 * s;
                    tma2d(base,                 &tmA, kc * KC,      m_base, mb);
                    tma2d(base + SUB_BYTES,     &tmA, kc * KC + 64, m_base, mb);
                    tma2d(base + 2 * SUB_BYTES, &tmB, kc * KC,      n_base, mb);
                    tma2d(base + 3 * SUB_BYTES, &tmB, kc * KC + 64, n_base, mb);
                    if (++s == STAGES) { s = 0; ph ^= 1; }
                }
            }
        }
    } else {                              // -------- 8 persistent compute warps --------
        const int m0 = (wid >> 1) * 32;
        const int n0 = (wid & 1) * 64;

        const int a_row = lid & 15;
        const int a_cof = (lid >> 4) << 4;
        const int b_row = ((lid >> 4) << 3) + (lid & 7);
        const int b_cof = ((lid >> 3) & 1) << 4;

        float acc[2][8][4];
        uint32_t af[2][2][4];
        uint32_t bf[2][4][4];

        auto loadfrag = [&](int buf, uint32_t stage, int step) {
            int st = step >> 2;
            int kk = step & 3;
            uint32_t baseA = stage + st * SUB_BYTES;
            uint32_t baseB = stage + (2 + st) * SUB_BYTES;
#pragma unroll
            for (int mt = 0; mt < 2; mt++) {
                int r = m0 + mt * 16 + a_row;
                int c = kk * 32 + a_cof;
                ldsm4(af[buf][mt], baseA + r * 128 + (c ^ ((r & 7) << 4)));
            }
#pragma unroll
            for (int np = 0; np < 4; np++) {
                int r = n0 + np * 16 + b_row;
                int c = kk * 32 + b_cof;
                ldsm4(bf[buf][np], baseB + r * 128 + (c ^ ((r & 7) << 4)));
            }
        };
        auto mmastep = [&](int buf) {
#pragma unroll
            for (int mt = 0; mt < 2; mt++)
#pragma unroll
                for (int nt = 0; nt < 8; nt++)
                    mma16816(acc[mt][nt], af[buf][mt], &bf[buf][nt >> 1][(nt & 1) * 2]);
        };

        const float scale = (__uint_as_float(absmax_bits[0]) / 127.0f) *
                            (__uint_as_float(absmax_bits[1]) / 127.0f);
        const int r4 = lid >> 2;
        const int c2 = (lid & 3) * 2;

        int s = 0, ph = 0;
        for (int t = blockIdx.x; t < ntiles; t += gridDim.x) {
            const int m_base = (t >> 3) * TM;
            const int n_base = (t & 7) * TN;

#pragma unroll
            for (int mt = 0; mt < 2; mt++)
#pragma unroll
                for (int nt = 0; nt < 8; nt++)
#pragma unroll
                    for (int j = 0; j < 4; j++) acc[mt][nt][j] = 0.0f;

            mbar_wait(sb + SM_MBAR + 16 * s, ph);
            uint32_t stage = sb + SM_A + s * STAGE_BYTES;
            loadfrag(0, stage, 0);

            for (int kc = 0; kc < KITERS; kc++) {
#pragma unroll
                for (int step = 0; step < 8; step++) {
                    const int pb = step & 1;
                    if (step < 7) {
                        loadfrag(pb ^ 1, stage, step + 1);
                    } else {
                        if (lid == 0) mbar_arrive(sb + SM_MBAR + 16 * s + 8);
                        if (++s == STAGES) { s = 0; ph ^= 1; }
                        if (kc < KITERS - 1) {
                            mbar_wait(sb + SM_MBAR + 16 * s, ph);
                            stage = sb + SM_A + s * STAGE_BYTES;
                            loadfrag(pb ^ 1, stage, 0);
                        }
                    }
                    mmastep(pb);
                }
            }

            // epilogue (producer already filling next tile's stages)
#pragma unroll
            for (int mt = 0; mt < 2; mt++) {
#pragma unroll
                for (int nt = 0; nt < 8; nt++) {
                    int cn = n0 + nt * 8 + c2;
                    float b0 = bias[n_base + cn];
                    float b1 = bias[n_base + cn + 1];
                    int gm = m_base + m0 + mt * 16 + r4;
                    float2 v0, v1;
                    v0.x = acc[mt][nt][0] * scale + b0;
                    v0.y = acc[mt][nt][1] * scale + b1;
                    v1.x = acc[mt][nt][2] * scale + b0;
                    v1.y = acc[mt][nt][3] * scale + b1;
                    *reinterpret_cast<float2*>(out + (size_t)gm * M_OUT + n_base + cn) = v0;
                    *reinterpret_cast<float2*>(out + (size_t)(gm + 8) * M_OUT + n_base + cn) = v1;
                }
            }
        }
    }
}

// ============================================================================
// Host launch
// ============================================================================
typedef CUresult (*tmap_encode_fn)(
    CUtensorMap*, CUtensorMapDataType, cuuint32_t, void*,
    const cuuint64_t*, const cuuint64_t*, const cuuint32_t*, const cuuint32_t*,
    CUtensorMapInterleave, CUtensorMapSwizzle, CUtensorMapL2promotion, CUtensorMapFloatOOBfill);

extern "C" void kernel_launch(void* const* d_in, const int* in_sizes, int n_in,
                              void* d_out, int out_size) {
    const float* x    = (const float*)d_in[0];
    const float* w    = (const float*)d_in[1];
    const float* bias = (const float*)d_in[2];
    float* out = (float*)d_out;

    int n_rows = in_sizes[0] / K_DIM;   // 32768
    int n4x = in_sizes[0] / 4;
    int n4w = in_sizes[1] / 4;
    int ntiles = (n_rows / TM) * NTILE_X;   // 2048

    void *qx_ptr, *qw_ptr, *am_ptr;
    cudaGetSymbolAddress(&qx_ptr, g_qx);
    cudaGetSymbolAddress(&qw_ptr, g_qw);
    cudaGetSymbolAddress(&am_ptr, g_absmax);
    unsigned* am = (unsigned*)am_ptr;

    prepass_kernel<<<PB, 256>>>((const float4*)x, (uint2*)qx_ptr, n4x,
                                (const float4*)w, (uint2*)qw_ptr, n4w, am);

    void* fp = nullptr;
    cudaDriverEntryPointQueryResult qr;
#if CUDART_VERSION >= 12050
    cudaGetDriverEntryPointByVersion("cuTensorMapEncodeTiled", &fp, 12000,
                                     cudaEnableDefault, &qr);
#else
    cudaGetDriverEntryPoint("cuTensorMapEncodeTiled", &fp, cudaEnableDefault, &qr);
#endif
    tmap_encode_fn encode = (tmap_encode_fn)fp;

    CUtensorMap tmA, tmB;
    {
        cuuint64_t dims[2]   = {K_DIM, (cuuint64_t)n_rows};
        cuuint64_t stride[1] = {K_DIM * sizeof(__nv_bfloat16)};
        cuuint32_t box[2]    = {64, TM};
        cuuint32_t es[2]     = {1, 1};
        encode(&tmA, CU_TENSOR_MAP_DATA_TYPE_BFLOAT16, 2, qx_ptr, dims, stride, box, es,
               CU_TENSOR_MAP_INTERLEAVE_NONE, CU_TENSOR_MAP_SWIZZLE_128B,
               CU_TENSOR_MAP_L2_PROMOTION_L2_128B, CU_TENSOR_MAP_FLOAT_OOB_FILL_NONE);
    }
    {
        cuuint64_t dims[2]   = {K_DIM, M_OUT};
        cuuint64_t stride[1] = {K_DIM * sizeof(__nv_bfloat16)};
        cuuint32_t box[2]    = {64, TN};
        cuuint32_t es[2]     = {1, 1};
        encode(&tmB, CU_TENSOR_MAP_DATA_TYPE_BFLOAT16, 2, qw_ptr, dims, stride, box, es,
               CU_TENSOR_MAP_INTERLEAVE_NONE, CU_TENSOR_MAP_SWIZZLE_128B,
               CU_TENSOR_MAP_L2_PROMOTION_L2_128B, CU_TENSOR_MAP_FLOAT_OOB_FILL_NONE);
    }

    int nsm = 148;
    cudaDeviceGetAttribute(&nsm, cudaDevAttrMultiProcessorCount, 0);

    cudaFuncSetAttribute(gemm_kernel, cudaFuncAttributeMaxDynamicSharedMemorySize, SMEM_TOTAL);
    gemm_kernel<<<nsm, NTHREADS, SMEM_TOTAL>>>(tmA, tmB, bias, out, am, ntiles);
}

// round 16
// speedup vs baseline: 1.2532x; 1.0056x over previous
#include <cuda_runtime.h>
#include <cuda.h>
#include <cuda_bf16.h>
#include <cstdint>

// ============================================================================
// Problem constants
// ============================================================================
#define K_DIM   1024
#define M_OUT   1024
#define N_MAX   32768

#define TM      128       // CTA tile rows
#define TN      128       // CTA tile cols
#define KC      128       // K elems per mainloop chunk (two 64-col SW128 sub-tiles)
#define STAGES  3
#define KITERS  (K_DIM / KC)    // 8 chunks per tile
#define NTHREADS 288            // 9 warps: 8 compute (32m x 64n each) + 1 TMA
#define NTILE_X (M_OUT / TN)    // 8 n-tiles

// SMEM layout (dynamic)
#define SM_MBAR  16                    // ring: full at 16+16s, empty at 24+16s
#define SM_A     1024
#define SUB_BYTES   16384              // one 128-row x 64-col bf16 sub-tile
#define STAGE_BYTES 65536              // A(2 sub) + B(2 sub)
#define SMEM_TOTAL (1024 + STAGES * STAGE_BYTES)   // 197632 < 227KB

// Persistent prepass grid: 6 blocks/SM x 148 SMs = 888, co-resident
#define XB 864
#define WB 24
#define PB (XB + WB)

// ============================================================================
// Scratch (__device__ globals; no allocation allowed)
// ============================================================================
__device__ __align__(1024) __nv_bfloat16 g_qx[(size_t)N_MAX * K_DIM];   // 64 MB
__device__ __align__(1024) __nv_bfloat16 g_qw[(size_t)M_OUT * K_DIM];   //  2 MB
__device__ unsigned g_absmax[2] = {0u, 0u};
__device__ unsigned g_arr_x = 0u;      // x-group barrier (864 CTAs)
__device__ unsigned g_arr_w = 0u;      // w-group barrier (24 CTAs)
__device__ unsigned g_done  = 0u;

// ============================================================================
// PTX helpers (base-target safe on sm_103)
// ============================================================================
__device__ __forceinline__ uint32_t smem_u32(const void* p) {
    return (uint32_t)__cvta_generic_to_shared(p);
}
__device__ __forceinline__ uint32_t elect1() {
    uint32_t pred;
    asm volatile("{\n\t.reg .pred p;\n\telect.sync _|p, 0xFFFFFFFF;\n\t"
                 "selp.b32 %0, 1, 0, p;\n\t}" : "=r"(pred));
    return pred;
}
__device__ __forceinline__ void mbar_init(uint32_t mbar, uint32_t count) {
    asm volatile("mbarrier.init.shared.b64 [%0], %1;" :: "r"(mbar), "r"(count) : "memory");
}
__device__ __forceinline__ void mbar_expect_tx(uint32_t mbar, uint32_t bytes) {
    asm volatile("mbarrier.arrive.expect_tx.shared.b64 _, [%0], %1;"
                 :: "r"(mbar), "r"(bytes) : "memory");
}
__device__ __forceinline__ void mbar_arrive(uint32_t mbar) {
    asm volatile("mbarrier.arrive.shared.b64 _, [%0];" :: "r"(mbar) : "memory");
}
__device__ __forceinline__ void mbar_wait(uint32_t mbar, uint32_t parity) {
    uint32_t done;
    asm volatile("{\n\t.reg .pred p;\n\t"
                 "mbarrier.try_wait.parity.acquire.cta.shared::cta.b64 p, [%1], %2;\n\t"
                 "selp.b32 %0, 1, 0, p;\n\t}"
                 : "=r"(done) : "r"(mbar), "r"(parity) : "memory");
    while (!done) {
        asm volatile("{\n\t.reg .pred p;\n\t"
                     "mbarrier.try_wait.parity.acquire.cta.shared::cta.b64 p, [%1], %2, 0x989680;\n\t"
                     "selp.b32 %0, 1, 0, p;\n\t}"
                     : "=r"(done) : "r"(mbar), "r"(parity) : "memory");
    }
}
__device__ __forceinline__ void tma2d(uint32_t dst, const CUtensorMap* tm,
                                      int cx, int cy, uint32_t mbar) {
    asm volatile("cp.async.bulk.tensor.2d.shared::cta.global.tile.mbarrier::complete_tx::bytes "
                 "[%0], [%1, {%2, %3}], [%4];"
                 :: "r"(dst), "l"(tm), "r"(cx), "r"(cy), "r"(mbar) : "memory");
}
__device__ __forceinline__ void ldsm4(uint32_t* r, uint32_t addr) {
    asm volatile("ldmatrix.sync.aligned.m8n8.x4.shared.b16 {%0,%1,%2,%3}, [%4];"
                 : "=r"(r[0]), "=r"(r[1]), "=r"(r[2]), "=r"(r[3]) : "r"(addr));
}
// legacy HMMA m16n8k16 bf16 -> f32 (int8 codes exact in bf16, accum < 2^24 exact
// in f32 -> bit-identical to int32 reference GEMM)
__device__ __forceinline__ void mma16816(float* c, const uint32_t* a, const uint32_t* b) {
    asm volatile("mma.sync.aligned.m16n8k16.row.col.f32.bf16.bf16.f32 "
                 "{%0,%1,%2,%3}, {%4,%5,%6,%7}, {%8,%9}, {%0,%1,%2,%3};"
                 : "+f"(c[0]), "+f"(c[1]), "+f"(c[2]), "+f"(c[3])
                 : "r"(a[0]), "r"(a[1]), "r"(a[2]), "r"(a[3]), "r"(b[0]), "r"(b[1]));
}
__device__ __forceinline__ uint2 quant4(float4 v, float inv) {
    float q0 = fminf(fmaxf(rintf(v.x * inv), -127.0f), 127.0f);
    float q1 = fminf(fmaxf(rintf(v.y * inv), -127.0f), 127.0f);
    float q2 = fminf(fmaxf(rintf(v.z * inv), -127.0f), 127.0f);
    float q3 = fminf(fmaxf(rintf(v.w * inv), -127.0f), 127.0f);
    __nv_bfloat162 p01 = __floats2bfloat162_rn(q0, q1);
    __nv_bfloat162 p23 = __floats2bfloat162_rn(q2, q3);
    uint2 o;
    o.x = *reinterpret_cast<uint32_t*>(&p01);
    o.y = *reinterpret_cast<uint32_t*>(&p23);
    return o;
}
// streaming (evict-first) stores: keep x / qx tiles resident in L2
__device__ __forceinline__ void st_cs_u2(uint2* p, uint2 v) {
    asm volatile("st.global.cs.v2.u32 [%0], {%1, %2};" :: "l"(p), "r"(v.x), "r"(v.y) : "memory");
}
__device__ __forceinline__ void st_cs_f2(float* p, float a, float b) {
    asm volatile("st.global.cs.v2.f32 [%0], {%1, %2};" :: "l"(p), "f"(a), "f"(b) : "memory");
}

// ============================================================================
// Persistent fused prepass (6 CTAs/SM): absmax -> per-group barrier -> quantize
//   x CTAs barrier only on x absmax (864), w CTAs only on w absmax (24) —
//   no cross-group straggler coupling; w quant overlaps x absmax tail.
//   Phase 2 iterates TOP-DOWN (phase-1 tail is L2-resident) with .cs stores
//   so quant writes don't evict the x data being harvested.
// ============================================================================
__global__ void __launch_bounds__(256, 6) prepass_kernel(
    const float4* __restrict__ x, uint2* __restrict__ qx, int n4x,
    const float4* __restrict__ w, uint2* __restrict__ qw, int n4w,
    unsigned* __restrict__ am)
{
    const float4* in; uint2* outq;
    int n4, nb, bid;
    unsigned* dst;
    unsigned* arr;
    unsigned cnt;
    if ((int)blockIdx.x < XB) {
        in = x; outq = qx; n4 = n4x; nb = XB; bid = blockIdx.x;
        dst = am;     arr = &g_arr_x; cnt = XB;
    } else {
        in = w; outq = qw; n4 = n4w; nb = WB; bid = blockIdx.x - XB;
        dst = am + 1; arr = &g_arr_w; cnt = WB;
    }

    const int stride = nb * blockDim.x;
    const int i0 = bid * blockDim.x + threadIdx.x;

    // ---- phase 1: absmax (MLP 8), ascending ----
    float m = 0.0f;
    int i = i0;
    for (; i + 7 * stride < n4; i += 8 * stride) {
        float pm[8];
#pragma unroll
        for (int u = 0; u < 8; u++) {
            float4 v = in[i + u * stride];
            pm[u] = fmaxf(fmaxf(fabsf(v.x), fabsf(v.y)), fmaxf(fabsf(v.z), fabsf(v.w)));
        }
        float m01 = fmaxf(pm[0], pm[1]), m23 = fmaxf(pm[2], pm[3]);
        float m45 = fmaxf(pm[4], pm[5]), m67 = fmaxf(pm[6], pm[7]);
        m = fmaxf(m, fmaxf(fmaxf(m01, m23), fmaxf(m45, m67)));
    }
    for (; i < n4; i += stride) {
        float4 v = in[i];
        m = fmaxf(m, fmaxf(fmaxf(fabsf(v.x), fabsf(v.y)), fmaxf(fabsf(v.z), fabsf(v.w))));
    }
#pragma unroll
    for (int o = 16; o > 0; o >>= 1)
        m = fmaxf(m, __shfl_xor_sync(0xFFFFFFFFu, m, o));
    if ((threadIdx.x & 31) == 0) atomicMax(dst, __float_as_uint(m));

    // ---- per-group grid barrier (all blocks co-resident: 6/SM) ----
    __syncthreads();
    if (threadIdx.x == 0) {
        __threadfence();
        atomicAdd(arr, 1u);
        while (*(volatile unsigned*)arr < cnt) { }
        __threadfence();
    }
    __syncthreads();

    // ---- phase 2: quantize (MLP 8), DESCENDING, streaming stores ----
    {
        float inv = 127.0f / __uint_as_float(*(volatile unsigned*)dst);
        int nit = (i0 < n4) ? ((n4 - i0 - 1) / stride + 1) : 0;
        int k = nit;
        while (k & 7) {
            --k;
            int idx = i0 + k * stride;
            st_cs_u2(&outq[idx], quant4(in[idx], inv));
        }
        while (k > 0) {
            k -= 8;
            float4 v[8];
#pragma unroll
            for (int u = 0; u < 8; u++) v[u] = in[i0 + (k + u) * stride];
#pragma unroll
            for (int u = 0; u < 8; u++) st_cs_u2(&outq[i0 + (k + u) * stride], quant4(v[u], inv));
        }
    }

    // ---- reset counters for deterministic graph replay ----
    __syncthreads();
    if (threadIdx.x == 0) {
        unsigned t = atomicAdd(&g_done, 1u);
        if (t == PB - 1) {
            g_arr_x = 0u;
            g_arr_w = 0u;
            g_done = 0u;
            __threadfence();
        }
    }
}

// ============================================================================
// PERSISTENT GEMM  out[m][n] = acc(m,n)*(sx*sw) + bias[n]   (R12/R15-proven)
//   grid = #SMs; producer streams TMA continuously across tile boundaries.
//   8 compute warps 4(m)x2(n), 32x64 each.  SW128 swizzle: c ^ ((r&7)<<4).
//   Epilogue uses .cs streaming stores (out never re-read -> protect qx in L2).
// ============================================================================
__global__ void __launch_bounds__(NTHREADS, 1) gemm_kernel(
    const __grid_constant__ CUtensorMap tmA,
    const __grid_constant__ CUtensorMap tmB,
    const float* __restrict__ bias,
    float* __restrict__ out,
    const unsigned* __restrict__ absmax_bits,
    int ntiles)
{
    extern __shared__ __align__(1024) char smem[];
    uint32_t sb = smem_u32(smem);
    const int tid = threadIdx.x;
    const int wid = tid >> 5;
    const int lid = tid & 31;

    if (tid == 0) {
        for (int s = 0; s < STAGES; s++) {
            mbar_init(sb + SM_MBAR + 16 * s, 1);       // full (producer expect_tx)
            mbar_init(sb + SM_MBAR + 16 * s + 8, 8);   // empty (8 compute warps)
        }
        asm volatile("fence.proxy.async.shared::cta;" ::: "memory");
    }
    __syncthreads();

    if (wid == 8) {                       // -------- persistent TMA producer --------
        if (elect1()) {
            int s = 0, ph = 1;
            for (int t = blockIdx.x; t < ntiles; t += gridDim.x) {
                const int m_base = (t >> 3) * TM;          // NTILE_X == 8
                const int n_base = (t & 7) * TN;
                for (int kc = 0; kc < KITERS; kc++) {
                    mbar_wait(sb + SM_MBAR + 16 * s + 8, ph);
                    mbar_expect_tx(sb + SM_MBAR + 16 * s, STAGE_BYTES);
                    uint32_t base = sb + SM_A + s * STAGE_BYTES;
                    uint32_t mb = sb + SM_MBAR + 16 * s;
                    tma2d(base,                 &tmA, kc * KC,      m_base, mb);
                    tma2d(base + SUB_BYTES,     &tmA, kc * KC + 64, m_base, mb);
                    tma2d(base + 2 * SUB_BYTES, &tmB, kc * KC,      n_base, mb);
                    tma2d(base + 3 * SUB_BYTES, &tmB, kc * KC + 64, n_base, mb);
                    if (++s == STAGES) { s = 0; ph ^= 1; }
                }
            }
        }
    } else {                              // -------- 8 persistent compute warps --------
        const int m0 = (wid >> 1) * 32;
        const int n0 = (wid & 1) * 64;

        const int a_row = lid & 15;
        const int a_cof = (lid >> 4) << 4;
        const int b_row = ((lid >> 4) << 3) + (lid & 7);
        const int b_cof = ((lid >> 3) & 1) << 4;

        float acc[2][8][4];
        uint32_t af[2][2][4];
        uint32_t bf[2][4][4];

        auto loadfrag = [&](int buf, uint32_t stage, int step) {
            int st = step >> 2;
            int kk = step & 3;
            uint32_t baseA = stage + st * SUB_BYTES;
            uint32_t baseB = stage + (2 + st) * SUB_BYTES;
#pragma unroll
            for (int mt = 0; mt < 2; mt++) {
                int r = m0 + mt * 16 + a_row;
                int c = kk * 32 + a_cof;
                ldsm4(af[buf][mt], baseA + r * 128 + (c ^ ((r & 7) << 4)));
            }
#pragma unroll
            for (int np = 0; np < 4; np++) {
                int r = n0 + np * 16 + b_row;
                int c = kk * 32 + b_cof;
                ldsm4(bf[buf][np], baseB + r * 128 + (c ^ ((r & 7) << 4)));
            }
        };
        auto mmastep = [&](int buf) {
#pragma unroll
            for (int mt = 0; mt < 2; mt++)
#pragma unroll
                for (int nt = 0; nt < 8; nt++)
                    mma16816(acc[mt][nt], af[buf][mt], &bf[buf][nt >> 1][(nt & 1) * 2]);
        };

        const float scale = (__uint_as_float(absmax_bits[0]) / 127.0f) *
                            (__uint_as_float(absmax_bits[1]) / 127.0f);
        const int r4 = lid >> 2;
        const int c2 = (lid & 3) * 2;

        int s = 0, ph = 0;
        for (int t = blockIdx.x; t < ntiles; t += gridDim.x) {
            const int m_base = (t >> 3) * TM;
            const int n_base = (t & 7) * TN;

#pragma unroll
            for (int mt = 0; mt < 2; mt++)
#pragma unroll
                for (int nt = 0; nt < 8; nt++)
#pragma unroll
                    for (int j = 0; j < 4; j++) acc[mt][nt][j] = 0.0f;

            mbar_wait(sb + SM_MBAR + 16 * s, ph);
            uint32_t stage = sb + SM_A + s * STAGE_BYTES;
            loadfrag(0, stage, 0);

            for (int kc = 0; kc < KITERS; kc++) {
#pragma unroll
                for (int step = 0; step < 8; step++) {
                    const int pb = step & 1;
                    if (step < 7) {
                        loadfrag(pb ^ 1, stage, step + 1);
                    } else {
                        if (lid == 0) mbar_arrive(sb + SM_MBAR + 16 * s + 8);
                        if (++s == STAGES) { s = 0; ph ^= 1; }
                        if (kc < KITERS - 1) {
                            mbar_wait(sb + SM_MBAR + 16 * s, ph);
                            stage = sb + SM_A + s * STAGE_BYTES;
                            loadfrag(pb ^ 1, stage, 0);
                        }
                    }
                    mmastep(pb);
                }
            }

            // epilogue: streaming stores (producer already filling next tile)
#pragma unroll
            for (int mt = 0; mt < 2; mt++) {
#pragma unroll
                for (int nt = 0; nt < 8; nt++) {
                    int cn = n0 + nt * 8 + c2;
                    float b0 = bias[n_base + cn];
                    float b1 = bias[n_base + cn + 1];
                    int gm = m_base + m0 + mt * 16 + r4;
                    st_cs_f2(out + (size_t)gm * M_OUT + n_base + cn,
                             acc[mt][nt][0] * scale + b0,
                             acc[mt][nt][1] * scale + b1);
                    st_cs_f2(out + (size_t)(gm + 8) * M_OUT + n_base + cn,
                             acc[mt][nt][2] * scale + b0,
                             acc[mt][nt][3] * scale + b1);
                }
            }
        }
    }
}

// ============================================================================
// Host launch
// ============================================================================
typedef CUresult (*tmap_encode_fn)(
    CUtensorMap*, CUtensorMapDataType, cuuint32_t, void*,
    const cuuint64_t*, const cuuint64_t*, const cuuint32_t*, const cuuint32_t*,
    CUtensorMapInterleave, CUtensorMapSwizzle, CUtensorMapL2promotion, CUtensorMapFloatOOBfill);

extern "C" void kernel_launch(void* const* d_in, const int* in_sizes, int n_in,
                              void* d_out, int out_size) {
    const float* x    = (const float*)d_in[0];
    const float* w    = (const float*)d_in[1];
    const float* bias = (const float*)d_in[2];
    float* out = (float*)d_out;

    int n_rows = in_sizes[0] / K_DIM;   // 32768
    int n4x = in_sizes[0] / 4;
    int n4w = in_sizes[1] / 4;
    int ntiles = (n_rows / TM) * NTILE_X;   // 2048

    void *qx_ptr, *qw_ptr, *am_ptr;
    cudaGetSymbolAddress(&qx_ptr, g_qx);
    cudaGetSymbolAddress(&qw_ptr, g_qw);
    cudaGetSymbolAddress(&am_ptr, g_absmax);
    unsigned* am = (unsigned*)am_ptr;

    prepass_kernel<<<PB, 256>>>((const float4*)x, (uint2*)qx_ptr, n4x,
                                (const float4*)w, (uint2*)qw_ptr, n4w, am);

    void* fp = nullptr;
    cudaDriverEntryPointQueryResult qr;
#if CUDART_VERSION >= 12050
    cudaGetDriverEntryPointByVersion("cuTensorMapEncodeTiled", &fp, 12000,
                                     cudaEnableDefault, &qr);
#else
    cudaGetDriverEntryPoint("cuTensorMapEncodeTiled", &fp, cudaEnableDefault, &qr);
#endif
    tmap_encode_fn encode = (tmap_encode_fn)fp;

    CUtensorMap tmA, tmB;
    {
        cuuint64_t dims[2]   = {K_DIM, (cuuint64_t)n_rows};
        cuuint64_t stride[1] = {K_DIM * sizeof(__nv_bfloat16)};
        cuuint32_t box[2]    = {64, TM};
        cuuint32_t es[2]     = {1, 1};
        encode(&tmA, CU_TENSOR_MAP_DATA_TYPE_BFLOAT16, 2, qx_ptr, dims, stride, box, es,
               CU_TENSOR_MAP_INTERLEAVE_NONE, CU_TENSOR_MAP_SWIZZLE_128B,
               CU_TENSOR_MAP_L2_PROMOTION_L2_128B, CU_TENSOR_MAP_FLOAT_OOB_FILL_NONE);
    }
    {
        cuuint64_t dims[2]   = {K_DIM, M_OUT};
        cuuint64_t stride[1] = {K_DIM * sizeof(__nv_bfloat16)};
        cuuint32_t box[2]    = {64, TN};
        cuuint32_t es[2]     = {1, 1};
        encode(&tmB, CU_TENSOR_MAP_DATA_TYPE_BFLOAT16, 2, qw_ptr, dims, stride, box, es,
               CU_TENSOR_MAP_INTERLEAVE_NONE, CU_TENSOR_MAP_SWIZZLE_128B,
               CU_TENSOR_MAP_L2_PROMOTION_L2_128B, CU_TENSOR_MAP_FLOAT_OOB_FILL_NONE);
    }

    int nsm = 148;
    cudaDeviceGetAttribute(&nsm, cudaDevAttrMultiProcessorCount, 0);

    cudaFuncSetAttribute(gemm_kernel, cudaFuncAttributeMaxDynamicSharedMemorySize, SMEM_TOTAL);
    gemm_kernel<<<nsm, NTHREADS, SMEM_TOTAL>>>(tmA, tmB, bias, out, am, ntiles);
}